// round 16
// baseline (speedup 1.0000x reference)
#include <cuda_runtime.h>
#include <cstdint>

// ---------------------------------------------------------------------------
// AllocationGNN: 3x GATConv + MLP head.  R16:
//  - 4-way head-split aggregation: per-pass gather working set = 25.6 MB
//    (5x margin inside L2); unroll-4 edge loop for gather MLP.
//  - everything else as R15 (cp.async TF32 GEMM, CSR gather, tf32 pre-round).
// ---------------------------------------------------------------------------

#define NMAX 50000
#define EMAX 800000
#define ETMAX (EMAX + NMAX)

__device__ float4 g_h_buf4[(size_t)NMAX * 128];    // N*512 floats (GEMM out)
__device__ float4 g_out_buf4[(size_t)NMAX * 128];  // N*512 floats (layer I/O)
__device__ float  g_sn_buf[NMAX * 4];
__device__ float  g_dn_buf[NMAX * 4];
__device__ float4 g_wc4[114688];                   // tf32-rounded W1|W2|W3
__device__ int    g_cnt[NMAX];
__device__ int    g_rp[NMAX + 1];
__device__ int    g_cursor[NMAX];
__device__ int    g_ssrc[ETMAX];
__device__ int    g_bsum[1024];

// ---- cache-policy helpers --------------------------------------------------

__device__ __forceinline__ uint64_t pol_last() {
    uint64_t p;
    asm("createpolicy.fractional.L2::evict_last.b64 %0, 1.0;" : "=l"(p));
    return p;
}
__device__ __forceinline__ uint64_t pol_first() {
    uint64_t p;
    asm("createpolicy.fractional.L2::evict_first.b64 %0, 1.0;" : "=l"(p));
    return p;
}
__device__ __forceinline__ float4 ld4_hint(const float4* a, uint64_t pol) {
    float4 v;
    asm("ld.global.nc.L2::cache_hint.v4.f32 {%0,%1,%2,%3}, [%4], %5;"
        : "=f"(v.x), "=f"(v.y), "=f"(v.z), "=f"(v.w)
        : "l"(a), "l"(pol));
    return v;
}
__device__ __forceinline__ void st4_hint(float4* a, float4 v, uint64_t pol) {
    asm volatile("st.global.L2::cache_hint.v4.f32 [%0], {%1,%2,%3,%4}, %5;"
                 :: "l"(a), "f"(v.x), "f"(v.y), "f"(v.z), "f"(v.w), "l"(pol)
                 : "memory");
}

// ---- misc helpers ----------------------------------------------------------

__device__ __forceinline__ uint32_t f2tf32(float f) {
    uint32_t r;
    asm("cvt.rna.tf32.f32 %0, %1;" : "=r"(r) : "f"(f));
    return r;
}
__device__ __forceinline__ float tf32r(float f) {
    return __uint_as_float(f2tf32(f));
}
__device__ __forceinline__ void mma_tf32(float* c, const uint32_t* a,
                                         const uint32_t* b) {
    asm volatile(
        "mma.sync.aligned.m16n8k8.row.col.f32.tf32.tf32.f32 "
        "{%0,%1,%2,%3}, {%4,%5,%6,%7}, {%8,%9}, {%0,%1,%2,%3};"
        : "+f"(c[0]), "+f"(c[1]), "+f"(c[2]), "+f"(c[3])
        : "r"(a[0]), "r"(a[1]), "r"(a[2]), "r"(a[3]), "r"(b[0]), "r"(b[1]));
}
__device__ __forceinline__ void cp16(void* d, const void* s, bool p) {
    uint32_t ds = (uint32_t)__cvta_generic_to_shared(d);
    int sz = p ? 16 : 0;
    asm volatile("cp.async.cg.shared.global [%0], [%1], 16, %2;"
                 :: "r"(ds), "l"(s), "r"(sz));
}
#define CP_COMMIT() asm volatile("cp.async.commit_group;")

// ---- tf32 pre-round (float4) ----------------------------------------------

__global__ void cvt4_k(const float4* __restrict__ in, float4* __restrict__ out,
                       int n4) {
    int i = blockIdx.x * blockDim.x + threadIdx.x;
    if (i >= n4) return;
    float4 v = in[i];
    v.x = tf32r(v.x); v.y = tf32r(v.y); v.z = tf32r(v.z); v.w = tf32r(v.w);
    out[i] = v;
}

// ---- CSR build -------------------------------------------------------------

__global__ void hist_k(const int* __restrict__ ei, int* __restrict__ cnt,
                       int E, int N) {
    int i = blockIdx.x * blockDim.x + threadIdx.x;
    if (i >= E + N) return;
    int dst = (i < E) ? ei[E + i] : (i - E);
    atomicAdd(&cnt[dst], 1);
}

__global__ void scan1(const int* __restrict__ cnt, int* __restrict__ rp,
                      int* __restrict__ bsum, int N) {
    __shared__ int sh[1024];
    int tid = threadIdx.x, gid = blockIdx.x * 1024 + tid;
    int v = (gid < N) ? cnt[gid] : 0;
    sh[tid] = v;
    __syncthreads();
    for (int off = 1; off < 1024; off <<= 1) {
        int t = (tid >= off) ? sh[tid - off] : 0;
        __syncthreads();
        sh[tid] += t;
        __syncthreads();
    }
    if (gid < N) rp[gid] = sh[tid] - v;
    if (tid == 1023) bsum[blockIdx.x] = sh[1023];
}

__global__ void scan2(int* __restrict__ bsum, int nb) {
    __shared__ int sh[1024];
    int tid = threadIdx.x;
    int v = (tid < nb) ? bsum[tid] : 0;
    sh[tid] = v;
    __syncthreads();
    for (int off = 1; off < 1024; off <<= 1) {
        int t = (tid >= off) ? sh[tid - off] : 0;
        __syncthreads();
        sh[tid] += t;
        __syncthreads();
    }
    if (tid < nb) bsum[tid] = sh[tid] - v;
}

__global__ void scan3(int* __restrict__ rp, const int* __restrict__ bsum,
                      int* __restrict__ cursor, int N, int ET) {
    int gid = blockIdx.x * blockDim.x + threadIdx.x;
    if (gid < N) {
        int r = rp[gid] + bsum[gid >> 10];
        rp[gid] = r;
        cursor[gid] = r;
    }
    if (gid == N) rp[N] = ET;
}

__global__ void scatter_k(const int* __restrict__ ei, int* __restrict__ cursor,
                          int* __restrict__ ssrc, int E, int N) {
    int i = blockIdx.x * blockDim.x + threadIdx.x;
    if (i >= E + N) return;
    int src, dst;
    if (i < E) { src = ei[i]; dst = ei[E + i]; }
    else       { src = dst = i - E; }
    int p = atomicAdd(&cursor[dst], 1);
    ssrc[p] = src;
}

// ---- TF32 GEMM, cp.async 3-stage: C[M,N] = A[M,K]*B[N,K]^T -----------------

__global__ __launch_bounds__(256, 2)
void sgemm_tf32(const float* __restrict__ A, const float* __restrict__ B,
                float* __restrict__ Cm, int M, int N, int K) {
    constexpr int BM = 128, BN = 128, BK = 16, ST = 3, LDS = BK + 4;
    extern __shared__ float smn[];
    float (*As)[BM][LDS] = reinterpret_cast<float(*)[BM][LDS]>(smn);
    float (*Bs)[BN][LDS] =
        reinterpret_cast<float(*)[BN][LDS]>(smn + ST * BM * LDS);
    const int tid  = threadIdx.x;
    const int warp = tid >> 5, lane = tid & 31;
    const int wm = warp >> 2, wn = warp & 3;
    const int g = lane >> 2, t4 = lane & 3;
    const int bm = blockIdx.y * BM, bn = blockIdx.x * BN;
    const int r0 = tid >> 2, c40 = (tid & 3) << 2, r1 = r0 + 64;
    const bool pa0 = (bm + r0) < M, pa1 = (bm + r1) < M;

    auto load_stage = [&](int s, int k0) {
        cp16(&As[s][r0][c40], A + (size_t)(bm + r0) * K + k0 + c40, pa0);
        cp16(&As[s][r1][c40], A + (size_t)(bm + r1) * K + k0 + c40, pa1);
        cp16(&Bs[s][r0][c40], B + (size_t)(bn + r0) * K + k0 + c40, true);
        cp16(&Bs[s][r1][c40], B + (size_t)(bn + r1) * K + k0 + c40, true);
        CP_COMMIT();
    };

    float c[4][4][4] = {};

    load_stage(0, 0);
    load_stage(1, BK);
    int st = 0;

    for (int k0 = 0; k0 < K; k0 += BK) {
        asm volatile("cp.async.wait_group 1;");
        __syncthreads();
        int kn = k0 + 2 * BK;
        if (kn < K) load_stage(st == 0 ? 2 : st - 1, kn);
        else        CP_COMMIT();

        #pragma unroll
        for (int ks = 0; ks < BK; ks += 8) {
            uint32_t af[4][4], bf[4][2];
            #pragma unroll
            for (int mi = 0; mi < 4; mi++) {
                int row = wm * 64 + mi * 16;
                af[mi][0] = __float_as_uint(As[st][row + g][ks + t4]);
                af[mi][1] = __float_as_uint(As[st][row + g + 8][ks + t4]);
                af[mi][2] = __float_as_uint(As[st][row + g][ks + t4 + 4]);
                af[mi][3] = __float_as_uint(As[st][row + g + 8][ks + t4 + 4]);
            }
            #pragma unroll
            for (int ni = 0; ni < 4; ni++) {
                int col = wn * 32 + ni * 8;
                bf[ni][0] = __float_as_uint(Bs[st][col + g][ks + t4]);
                bf[ni][1] = __float_as_uint(Bs[st][col + g][ks + t4 + 4]);
            }
            #pragma unroll
            for (int mi = 0; mi < 4; mi++)
                #pragma unroll
                for (int ni = 0; ni < 4; ni++)
                    mma_tf32(c[mi][ni], af[mi], bf[ni]);
        }
        st = (st == ST - 1) ? 0 : st + 1;
    }

    #pragma unroll
    for (int mi = 0; mi < 4; mi++) {
        int row0 = bm + wm * 64 + mi * 16 + g;
        #pragma unroll
        for (int ni = 0; ni < 4; ni++) {
            int col = bn + wn * 32 + ni * 8 + t4 * 2;
            if (row0 < M)
                *reinterpret_cast<float2*>(Cm + (size_t)row0 * N + col) =
                    make_float2(c[mi][ni][0], c[mi][ni][1]);
            if (row0 + 8 < M)
                *reinterpret_cast<float2*>(Cm + (size_t)(row0 + 8) * N + col) =
                    make_float2(c[mi][ni][2], c[mi][ni][3]);
        }
    }
}

// ---- attention coefficients: s_n, d_n (warp per (node,head), float4) -------

__global__ void compute_sd(const float4* __restrict__ h,
                           const float4* __restrict__ a_src,
                           const float4* __restrict__ a_dst,
                           float* __restrict__ sn, float* __restrict__ dn,
                           int N, int H) {
    int w = (blockIdx.x * blockDim.x + threadIdx.x) >> 5;
    int lane = threadIdx.x & 31;
    if (w >= N * H) return;
    int n = w / H, hh = w - n * H;
    float4 v  = h[(size_t)n * H * 32 + hh * 32 + lane];
    float4 as = a_src[hh * 32 + lane];
    float4 ad = a_dst[hh * 32 + lane];
    float s = v.x * as.x + v.y * as.y + v.z * as.z + v.w * as.w;
    float d = v.x * ad.x + v.y * ad.y + v.z * ad.z + v.w * ad.w;
    #pragma unroll
    for (int o = 16; o; o >>= 1) {
        s += __shfl_down_sync(0xffffffffu, s, o);
        d += __shfl_down_sync(0xffffffffu, d, o);
    }
    if (lane == 0) { sn[w] = s; dn[w] = d; }
}

// ---- single-head gather aggregation: warp per node, one head per pass ------
// Per-pass gather working set = N*128 floats = 25.6 MB (fits L2 with margin).
// Edge loop unrolled 4x for gather MLP.  h reads evict_last; out evict_first.

__global__ void aggregate1_k(const int* __restrict__ rp,
                             const int* __restrict__ ssrc,
                             const float4* __restrict__ hf,
                             const float* __restrict__ sn,
                             const float* __restrict__ dn,
                             const float4* __restrict__ bias, int act,
                             float4* __restrict__ outp, int N,
                             int HTOT, int h0) {
    int n = (blockIdx.x * blockDim.x + threadIdx.x) >> 5;
    int lane = threadIdx.x & 31;
    if (n >= N) return;
    uint64_t pl = pol_last();
    uint64_t pf = pol_first();
    const int rowJ = HTOT * 32;              // float4 per full node row
    const int off  = h0 * 32 + lane;         // this lane's chunk

    float dnv = dn[n * HTOT + h0];           // same for all lanes (broadcast ld)

    float4 acc = make_float4(0.f, 0.f, 0.f, 0.f);
    float den = 0.f;

    const int s0 = rp[n], s1 = rp[n + 1];
    int p = s0;
    for (; p + 3 < s1; p += 4) {
        int srcA = __ldg(ssrc + p + 0);
        int srcB = __ldg(ssrc + p + 1);
        int srcC = __ldg(ssrc + p + 2);
        int srcD = __ldg(ssrc + p + 3);
        // every lane computes the same exp (cheap; avoids shfl dependency)
        float eA = sn[srcA * HTOT + h0] + dnv;
        float eB = sn[srcB * HTOT + h0] + dnv;
        float eC = sn[srcC * HTOT + h0] + dnv;
        float eD = sn[srcD * HTOT + h0] + dnv;
        eA = eA > 0.f ? eA : 0.2f * eA;  eB = eB > 0.f ? eB : 0.2f * eB;
        eC = eC > 0.f ? eC : 0.2f * eC;  eD = eD > 0.f ? eD : 0.2f * eD;
        float exA = __expf(eA), exB = __expf(eB);
        float exC = __expf(eC), exD = __expf(eD);
        den += (exA + exB) + (exC + exD);
        float4 va = ld4_hint(hf + (size_t)srcA * rowJ + off, pl);
        float4 vb = ld4_hint(hf + (size_t)srcB * rowJ + off, pl);
        float4 vc = ld4_hint(hf + (size_t)srcC * rowJ + off, pl);
        float4 vd = ld4_hint(hf + (size_t)srcD * rowJ + off, pl);
        acc.x += exA * va.x + exB * vb.x + exC * vc.x + exD * vd.x;
        acc.y += exA * va.y + exB * vb.y + exC * vc.y + exD * vd.y;
        acc.z += exA * va.z + exB * vb.z + exC * vc.z + exD * vd.z;
        acc.w += exA * va.w + exB * vb.w + exC * vc.w + exD * vd.w;
    }
    for (; p < s1; p++) {
        int src = __ldg(ssrc + p);
        float e = sn[src * HTOT + h0] + dnv;
        e = e > 0.f ? e : 0.2f * e;
        float ex = __expf(e);
        den += ex;
        float4 v = ld4_hint(hf + (size_t)src * rowJ + off, pl);
        acc.x += ex * v.x; acc.y += ex * v.y;
        acc.z += ex * v.z; acc.w += ex * v.w;
    }

    float sc = 1.f / (den + 1e-16f);
    float4 bb = bias[off];
    float4 v;
    v.x = acc.x * sc + bb.x;
    v.y = acc.y * sc + bb.y;
    v.z = acc.z * sc + bb.z;
    v.w = acc.w * sc + bb.w;
    if (act) {
        v.x = v.x > 0.f ? v.x : (__expf(v.x) - 1.f);
        v.y = v.y > 0.f ? v.y : (__expf(v.y) - 1.f);
        v.z = v.z > 0.f ? v.z : (__expf(v.z) - 1.f);
        v.w = v.w > 0.f ? v.w : (__expf(v.w) - 1.f);
        v.x = tf32r(v.x); v.y = tf32r(v.y);
        v.z = tf32r(v.z); v.w = tf32r(v.w);
        st4_hint(outp + (size_t)n * rowJ + off, v, pf);
    } else {
        outp[(size_t)n * rowJ + off] = v;
    }
}

// ---- MLP head --------------------------------------------------------------

__global__ __launch_bounds__(64)
void head_kernel(const float* __restrict__ emb, const float* __restrict__ Wh1,
                 const float* __restrict__ bh1, const float* __restrict__ Wh2,
                 const float* __restrict__ bh2, float* __restrict__ scores, int N) {
    int n = blockIdx.x;
    int j = threadIdx.x;
    __shared__ float er[128];
    __shared__ float zs[64];
    er[j]      = emb[(size_t)n * 128 + j];
    er[j + 64] = emb[(size_t)n * 128 + 64 + j];
    __syncthreads();
    const float* w = Wh1 + j * 128;
    float s = 0.f;
    #pragma unroll 8
    for (int k = 0; k < 128; k++) s += er[k] * w[k];
    s += bh1[j];
    s = fmaxf(s, 0.f);
    zs[j] = s * Wh2[j];
    __syncthreads();
    if (j < 32) {
        float v = zs[j] + zs[j + 32];
        #pragma unroll
        for (int o = 16; o; o >>= 1) v += __shfl_down_sync(0xffffffffu, v, o);
        if (j == 0) scores[n] = 1.f / (1.f + __expf(-(v + bh2[0])));
    }
}

// ---------------------------------------------------------------------------

extern "C" void kernel_launch(void* const* d_in, const int* in_sizes, int n_in,
                              void* d_out, int out_size) {
    const float* x  = (const float*)d_in[0];
    const int*   ei = (const int*)d_in[1];
    const float *W1 = (const float*)d_in[2],  *as1 = (const float*)d_in[3],
                *ad1 = (const float*)d_in[4], *b1 = (const float*)d_in[5];
    const float *W2 = (const float*)d_in[6],  *as2 = (const float*)d_in[7],
                *ad2 = (const float*)d_in[8], *b2 = (const float*)d_in[9];
    const float *W3 = (const float*)d_in[10], *as3 = (const float*)d_in[11],
                *ad3 = (const float*)d_in[12], *b3 = (const float*)d_in[13];
    const float *Wh1 = (const float*)d_in[14], *bh1 = (const float*)d_in[15],
                *Wh2 = (const float*)d_in[16], *bh2 = (const float*)d_in[17];
    float* out = (float*)d_out;

    const int N = in_sizes[0] / 256;
    const int E = in_sizes[1] / 2;
    const int ET = E + N;

    float4 *gh4, *gout4, *wc4;
    float *snp, *dnp;
    int *cnt, *rp, *cursor, *ssrc, *bsum;
    cudaGetSymbolAddress((void**)&gh4,    g_h_buf4);
    cudaGetSymbolAddress((void**)&gout4,  g_out_buf4);
    cudaGetSymbolAddress((void**)&wc4,    g_wc4);
    cudaGetSymbolAddress((void**)&snp,    g_sn_buf);
    cudaGetSymbolAddress((void**)&dnp,    g_dn_buf);
    cudaGetSymbolAddress((void**)&cnt,    g_cnt);
    cudaGetSymbolAddress((void**)&rp,     g_rp);
    cudaGetSymbolAddress((void**)&cursor, g_cursor);
    cudaGetSymbolAddress((void**)&ssrc,   g_ssrc);
    cudaGetSymbolAddress((void**)&bsum,   g_bsum);
    float* gout = (float*)gout4;

    auto cdiv = [](int a, int b) { return (a + b - 1) / b; };

    constexpr int SMEM_GEMM = 3 * 128 * 20 * 2 * 4;   // 61440 B
    cudaFuncSetAttribute(sgemm_tf32,
                         cudaFuncAttributeMaxDynamicSharedMemorySize, SMEM_GEMM);

    // ---- pre-round weights + x to tf32 bits ----
    float* wc1 = (float*)wc4;
    float* wc2 = wc1 + 131072;
    float* wc3 = wc2 + 262144;
    cvt4_k<<<cdiv(131072 / 4, 256), 256>>>((const float4*)W1, (float4*)wc1, 131072 / 4);
    cvt4_k<<<cdiv(262144 / 4, 256), 256>>>((const float4*)W2, (float4*)wc2, 262144 / 4);
    cvt4_k<<<cdiv(65536 / 4, 256), 256>>>((const float4*)W3, (float4*)wc3, 65536 / 4);
    float* xc = gout;
    cvt4_k<<<cdiv(N * 64, 256), 256>>>((const float4*)x, (float4*)xc, N * 64);

    // ---- CSR build (once; reused by all 3 layers) ----
    const int nb = cdiv(N, 1024);
    cudaMemsetAsync(cnt, 0, (size_t)N * 4);
    hist_k<<<cdiv(ET, 256), 256>>>(ei, cnt, E, N);
    scan1<<<nb, 1024>>>(cnt, rp, bsum, N);
    scan2<<<1, 1024>>>(bsum, nb);
    scan3<<<cdiv(N + 1, 256), 256>>>(rp, bsum, cursor, N, ET);
    scatter_k<<<cdiv(ET, 256), 256>>>(ei, cursor, ssrc, E, N);

    // ---- generic GAT layer ----
    auto run_layer = [&](const float* fin, int Fin, const float* W,
                         const float* as, const float* ad, const float* bb,
                         int H, int act, float* finalout) {
        const int HC = H * 128;
        dim3 gg(cdiv(HC, 128), cdiv(N, 128));
        sgemm_tf32<<<gg, 256, SMEM_GEMM>>>(fin, W, (float*)gh4, N, HC, Fin);
        compute_sd<<<cdiv(N * H * 32, 256), 256>>>(
            (const float4*)gh4, (const float4*)as, (const float4*)ad,
            snp, dnp, N, H);
        int agg_grid = cdiv(N * 32, 256);
        for (int h0 = 0; h0 < H; h0++)
            aggregate1_k<<<agg_grid, 256>>>(
                rp, ssrc, gh4, snp, dnp, (const float4*)bb, act,
                (float4*)finalout, N, H, h0);
    };

    run_layer(xc,   256, wc1, as1, ad1, b1, 4, 1, gout);
    run_layer(gout, 512, wc2, as2, ad2, b2, 4, 1, gout);
    run_layer(gout, 512, wc3, as3, ad3, b3, 1, 0, out);

    head_kernel<<<N, 64>>>(out, Wh1, bh1, Wh2, bh2, out + (size_t)N * 128, N);
}

// round 17
// speedup vs baseline: 1.0375x; 1.0375x over previous
#include <cuda_runtime.h>
#include <cuda_fp16.h>
#include <cstdint>

// ---------------------------------------------------------------------------
// AllocationGNN: 3x GATConv + MLP head.  R17:
//  - h stored as fp16 (same 10-bit mantissa as tf32): gather traffic halved,
//    full H=4 working set = 51 MB fits L2 in ONE aggregation pass per layer
//    (head-splitting removed).  fp32 accumulation everywhere.
//  - GEMM unchanged (cp.async tf32) except fp16-converting epilogue.
// ---------------------------------------------------------------------------

#define NMAX 50000
#define EMAX 800000
#define ETMAX (EMAX + NMAX)

__device__ float4 g_h_buf4[(size_t)NMAX * 128];    // holds h as half [N*512]
__device__ float4 g_out_buf4[(size_t)NMAX * 128];  // N*512 floats (layer I/O)
__device__ float  g_sn_buf[NMAX * 4];
__device__ float  g_dn_buf[NMAX * 4];
__device__ float4 g_wc4[114688];                   // tf32-rounded W1|W2|W3
__device__ int    g_cnt[NMAX];
__device__ int    g_rp[NMAX + 1];
__device__ int    g_cursor[NMAX];
__device__ int    g_ssrc[ETMAX];
__device__ int    g_bsum[1024];

// ---- cache-policy helpers --------------------------------------------------

__device__ __forceinline__ uint64_t pol_last() {
    uint64_t p;
    asm("createpolicy.fractional.L2::evict_last.b64 %0, 1.0;" : "=l"(p));
    return p;
}
__device__ __forceinline__ uint64_t pol_first() {
    uint64_t p;
    asm("createpolicy.fractional.L2::evict_first.b64 %0, 1.0;" : "=l"(p));
    return p;
}
__device__ __forceinline__ uint2 ld8_hint(const uint2* a, uint64_t pol) {
    uint2 u;
    asm("ld.global.nc.L2::cache_hint.v2.u32 {%0,%1}, [%2], %3;"
        : "=r"(u.x), "=r"(u.y) : "l"(a), "l"(pol));
    return u;
}
__device__ __forceinline__ void st4_hint(float4* a, float4 v, uint64_t pol) {
    asm volatile("st.global.L2::cache_hint.v4.f32 [%0], {%1,%2,%3,%4}, %5;"
                 :: "l"(a), "f"(v.x), "f"(v.y), "f"(v.z), "f"(v.w), "l"(pol)
                 : "memory");
}

// ---- misc helpers ----------------------------------------------------------

__device__ __forceinline__ uint32_t f2tf32(float f) {
    uint32_t r;
    asm("cvt.rna.tf32.f32 %0, %1;" : "=r"(r) : "f"(f));
    return r;
}
__device__ __forceinline__ float tf32r(float f) {
    return __uint_as_float(f2tf32(f));
}
__device__ __forceinline__ void mma_tf32(float* c, const uint32_t* a,
                                         const uint32_t* b) {
    asm volatile(
        "mma.sync.aligned.m16n8k8.row.col.f32.tf32.tf32.f32 "
        "{%0,%1,%2,%3}, {%4,%5,%6,%7}, {%8,%9}, {%0,%1,%2,%3};"
        : "+f"(c[0]), "+f"(c[1]), "+f"(c[2]), "+f"(c[3])
        : "r"(a[0]), "r"(a[1]), "r"(a[2]), "r"(a[3]), "r"(b[0]), "r"(b[1]));
}
__device__ __forceinline__ void cp16(void* d, const void* s, bool p) {
    uint32_t ds = (uint32_t)__cvta_generic_to_shared(d);
    int sz = p ? 16 : 0;
    asm volatile("cp.async.cg.shared.global [%0], [%1], 16, %2;"
                 :: "r"(ds), "l"(s), "r"(sz));
}
#define CP_COMMIT() asm volatile("cp.async.commit_group;")

// ---- tf32 pre-round (float4) ----------------------------------------------

__global__ void cvt4_k(const float4* __restrict__ in, float4* __restrict__ out,
                       int n4) {
    int i = blockIdx.x * blockDim.x + threadIdx.x;
    if (i >= n4) return;
    float4 v = in[i];
    v.x = tf32r(v.x); v.y = tf32r(v.y); v.z = tf32r(v.z); v.w = tf32r(v.w);
    out[i] = v;
}

// ---- CSR build -------------------------------------------------------------

__global__ void hist_k(const int* __restrict__ ei, int* __restrict__ cnt,
                       int E, int N) {
    int i = blockIdx.x * blockDim.x + threadIdx.x;
    if (i >= E + N) return;
    int dst = (i < E) ? ei[E + i] : (i - E);
    atomicAdd(&cnt[dst], 1);
}

__global__ void scan1(const int* __restrict__ cnt, int* __restrict__ rp,
                      int* __restrict__ bsum, int N) {
    __shared__ int sh[1024];
    int tid = threadIdx.x, gid = blockIdx.x * 1024 + tid;
    int v = (gid < N) ? cnt[gid] : 0;
    sh[tid] = v;
    __syncthreads();
    for (int off = 1; off < 1024; off <<= 1) {
        int t = (tid >= off) ? sh[tid - off] : 0;
        __syncthreads();
        sh[tid] += t;
        __syncthreads();
    }
    if (gid < N) rp[gid] = sh[tid] - v;
    if (tid == 1023) bsum[blockIdx.x] = sh[1023];
}

__global__ void scan2(int* __restrict__ bsum, int nb) {
    __shared__ int sh[1024];
    int tid = threadIdx.x;
    int v = (tid < nb) ? bsum[tid] : 0;
    sh[tid] = v;
    __syncthreads();
    for (int off = 1; off < 1024; off <<= 1) {
        int t = (tid >= off) ? sh[tid - off] : 0;
        __syncthreads();
        sh[tid] += t;
        __syncthreads();
    }
    if (tid < nb) bsum[tid] = sh[tid] - v;
}

__global__ void scan3(int* __restrict__ rp, const int* __restrict__ bsum,
                      int* __restrict__ cursor, int N, int ET) {
    int gid = blockIdx.x * blockDim.x + threadIdx.x;
    if (gid < N) {
        int r = rp[gid] + bsum[gid >> 10];
        rp[gid] = r;
        cursor[gid] = r;
    }
    if (gid == N) rp[N] = ET;
}

__global__ void scatter_k(const int* __restrict__ ei, int* __restrict__ cursor,
                          int* __restrict__ ssrc, int E, int N) {
    int i = blockIdx.x * blockDim.x + threadIdx.x;
    if (i >= E + N) return;
    int src, dst;
    if (i < E) { src = ei[i]; dst = ei[E + i]; }
    else       { src = dst = i - E; }
    int p = atomicAdd(&cursor[dst], 1);
    ssrc[p] = src;
}

// ---- TF32 GEMM, cp.async 3-stage; fp16 output ------------------------------
// C[M,N] = A[M,K]*B[N,K]^T, A/B fp32 (tf32-rounded), C stored as __half.

__global__ __launch_bounds__(256, 2)
void sgemm_tf32(const float* __restrict__ A, const float* __restrict__ B,
                __half* __restrict__ Ch, int M, int N, int K) {
    constexpr int BM = 128, BN = 128, BK = 16, ST = 3, LDS = BK + 4;
    extern __shared__ float smn[];
    float (*As)[BM][LDS] = reinterpret_cast<float(*)[BM][LDS]>(smn);
    float (*Bs)[BN][LDS] =
        reinterpret_cast<float(*)[BN][LDS]>(smn + ST * BM * LDS);
    const int tid  = threadIdx.x;
    const int warp = tid >> 5, lane = tid & 31;
    const int wm = warp >> 2, wn = warp & 3;
    const int g = lane >> 2, t4 = lane & 3;
    const int bm = blockIdx.y * BM, bn = blockIdx.x * BN;
    const int r0 = tid >> 2, c40 = (tid & 3) << 2, r1 = r0 + 64;
    const bool pa0 = (bm + r0) < M, pa1 = (bm + r1) < M;

    auto load_stage = [&](int s, int k0) {
        cp16(&As[s][r0][c40], A + (size_t)(bm + r0) * K + k0 + c40, pa0);
        cp16(&As[s][r1][c40], A + (size_t)(bm + r1) * K + k0 + c40, pa1);
        cp16(&Bs[s][r0][c40], B + (size_t)(bn + r0) * K + k0 + c40, true);
        cp16(&Bs[s][r1][c40], B + (size_t)(bn + r1) * K + k0 + c40, true);
        CP_COMMIT();
    };

    float c[4][4][4] = {};

    load_stage(0, 0);
    load_stage(1, BK);
    int st = 0;

    for (int k0 = 0; k0 < K; k0 += BK) {
        asm volatile("cp.async.wait_group 1;");
        __syncthreads();
        int kn = k0 + 2 * BK;
        if (kn < K) load_stage(st == 0 ? 2 : st - 1, kn);
        else        CP_COMMIT();

        #pragma unroll
        for (int ks = 0; ks < BK; ks += 8) {
            uint32_t af[4][4], bf[4][2];
            #pragma unroll
            for (int mi = 0; mi < 4; mi++) {
                int row = wm * 64 + mi * 16;
                af[mi][0] = __float_as_uint(As[st][row + g][ks + t4]);
                af[mi][1] = __float_as_uint(As[st][row + g + 8][ks + t4]);
                af[mi][2] = __float_as_uint(As[st][row + g][ks + t4 + 4]);
                af[mi][3] = __float_as_uint(As[st][row + g + 8][ks + t4 + 4]);
            }
            #pragma unroll
            for (int ni = 0; ni < 4; ni++) {
                int col = wn * 32 + ni * 8;
                bf[ni][0] = __float_as_uint(Bs[st][col + g][ks + t4]);
                bf[ni][1] = __float_as_uint(Bs[st][col + g][ks + t4 + 4]);
            }
            #pragma unroll
            for (int mi = 0; mi < 4; mi++)
                #pragma unroll
                for (int ni = 0; ni < 4; ni++)
                    mma_tf32(c[mi][ni], af[mi], bf[ni]);
        }
        st = (st == ST - 1) ? 0 : st + 1;
    }

    #pragma unroll
    for (int mi = 0; mi < 4; mi++) {
        int row0 = bm + wm * 64 + mi * 16 + g;
        #pragma unroll
        for (int ni = 0; ni < 4; ni++) {
            int col = bn + wn * 32 + ni * 8 + t4 * 2;
            if (row0 < M)
                *reinterpret_cast<__half2*>(Ch + (size_t)row0 * N + col) =
                    __floats2half2_rn(c[mi][ni][0], c[mi][ni][1]);
            if (row0 + 8 < M)
                *reinterpret_cast<__half2*>(Ch + (size_t)(row0 + 8) * N + col) =
                    __floats2half2_rn(c[mi][ni][2], c[mi][ni][3]);
        }
    }
}

// ---- attention coefficients from fp16 h ------------------------------------
// warp per (node,head); lane loads 4 halves (uint2) + float4 of a vectors.

__global__ void compute_sd(const uint2* __restrict__ h,
                           const float4* __restrict__ a_src,
                           const float4* __restrict__ a_dst,
                           float* __restrict__ sn, float* __restrict__ dn,
                           int N, int H) {
    int w = (blockIdx.x * blockDim.x + threadIdx.x) >> 5;
    int lane = threadIdx.x & 31;
    if (w >= N * H) return;
    int n = w / H, hh = w - n * H;
    uint2 u = h[(size_t)n * H * 32 + hh * 32 + lane];
    float2 f0 = __half22float2(*reinterpret_cast<__half2*>(&u.x));
    float2 f1 = __half22float2(*reinterpret_cast<__half2*>(&u.y));
    float4 as = a_src[hh * 32 + lane];
    float4 ad = a_dst[hh * 32 + lane];
    float s = f0.x * as.x + f0.y * as.y + f1.x * as.z + f1.y * as.w;
    float d = f0.x * ad.x + f0.y * ad.y + f1.x * ad.z + f1.y * ad.w;
    #pragma unroll
    for (int o = 16; o; o >>= 1) {
        s += __shfl_down_sync(0xffffffffu, s, o);
        d += __shfl_down_sync(0xffffffffu, d, o);
    }
    if (lane == 0) { sn[w] = s; dn[w] = d; }
}

// ---- fp16 gather aggregation: warp per node, ALL heads in one pass ---------
// Row = H*128 halves = H*32 uint2; lane owns H uint2 (one head each).
// fp32 accumulate; epilogue: 1/den, bias, optional ELU+tf32 round; fp32 out.

template <int H>
__global__ void aggregate_h(const int* __restrict__ rp,
                            const int* __restrict__ ssrc,
                            const uint2* __restrict__ hf,
                            const float* __restrict__ sn,
                            const float* __restrict__ dn,
                            const float4* __restrict__ bias, int act,
                            float4* __restrict__ outp, int N) {
    const int rowU = H * 32;             // uint2 per node row
    int n = (blockIdx.x * blockDim.x + threadIdx.x) >> 5;
    int lane = threadIdx.x & 31;
    if (n >= N) return;
    const int head = (lane * H) >> 5;    // H=4: lane>>3, H=1: 0
    uint64_t pl = pol_last();
    uint64_t pf = pol_first();
    const int base = lane * H;           // lane's first uint2 in row

    float dnv = (lane < H) ? dn[n * H + lane] : 0.f;

    float4 acc[H];
    #pragma unroll
    for (int it = 0; it < H; it++) acc[it] = make_float4(0.f, 0.f, 0.f, 0.f);
    float den = 0.f;

    const int s0 = rp[n], s1 = rp[n + 1];
    int p = s0;
    for (; p + 1 < s1; p += 2) {
        int srcA = __ldg(ssrc + p);
        int srcB = __ldg(ssrc + p + 1);
        float exvA = 0.f, exvB = 0.f;
        if (lane < H) {
            float eA = sn[srcA * H + lane] + dnv;
            float eB = sn[srcB * H + lane] + dnv;
            eA = eA > 0.f ? eA : 0.2f * eA;
            eB = eB > 0.f ? eB : 0.2f * eB;
            exvA = __expf(eA);
            exvB = __expf(eB);
        }
        float exA = __shfl_sync(0xffffffffu, exvA, head);
        float exB = __shfl_sync(0xffffffffu, exvB, head);
        den += exA + exB;
        const uint2* ra = hf + (size_t)srcA * rowU + base;
        const uint2* rb = hf + (size_t)srcB * rowU + base;
        #pragma unroll
        for (int it = 0; it < H; it++) {
            uint2 ua = ld8_hint(ra + it, pl);
            uint2 ub = ld8_hint(rb + it, pl);
            float2 a0 = __half22float2(*reinterpret_cast<__half2*>(&ua.x));
            float2 a1 = __half22float2(*reinterpret_cast<__half2*>(&ua.y));
            float2 b0 = __half22float2(*reinterpret_cast<__half2*>(&ub.x));
            float2 b1 = __half22float2(*reinterpret_cast<__half2*>(&ub.y));
            acc[it].x += exA * a0.x + exB * b0.x;
            acc[it].y += exA * a0.y + exB * b0.y;
            acc[it].z += exA * a1.x + exB * b1.x;
            acc[it].w += exA * a1.y + exB * b1.y;
        }
    }
    if (p < s1) {
        int src = __ldg(ssrc + p);
        float exv = 0.f;
        if (lane < H) {
            float e = sn[src * H + lane] + dnv;
            e = e > 0.f ? e : 0.2f * e;
            exv = __expf(e);
        }
        float ex = __shfl_sync(0xffffffffu, exv, head);
        den += ex;
        const uint2* hrow = hf + (size_t)src * rowU + base;
        #pragma unroll
        for (int it = 0; it < H; it++) {
            uint2 u = ld8_hint(hrow + it, pl);
            float2 f0 = __half22float2(*reinterpret_cast<__half2*>(&u.x));
            float2 f1 = __half22float2(*reinterpret_cast<__half2*>(&u.y));
            acc[it].x += ex * f0.x; acc[it].y += ex * f0.y;
            acc[it].z += ex * f1.x; acc[it].w += ex * f1.y;
        }
    }

    float sc = 1.f / (den + 1e-16f);
    float4* orow = outp + (size_t)n * (H * 32) + base;
    #pragma unroll
    for (int it = 0; it < H; it++) {
        float4 bb = bias[base + it];
        float4 v;
        v.x = acc[it].x * sc + bb.x;
        v.y = acc[it].y * sc + bb.y;
        v.z = acc[it].z * sc + bb.z;
        v.w = acc[it].w * sc + bb.w;
        if (act) {
            v.x = v.x > 0.f ? v.x : (__expf(v.x) - 1.f);
            v.y = v.y > 0.f ? v.y : (__expf(v.y) - 1.f);
            v.z = v.z > 0.f ? v.z : (__expf(v.z) - 1.f);
            v.w = v.w > 0.f ? v.w : (__expf(v.w) - 1.f);
            v.x = tf32r(v.x); v.y = tf32r(v.y);
            v.z = tf32r(v.z); v.w = tf32r(v.w);
            st4_hint(orow + it, v, pf);
        } else {
            orow[it] = v;
        }
    }
}

// ---- MLP head --------------------------------------------------------------

__global__ __launch_bounds__(64)
void head_kernel(const float* __restrict__ emb, const float* __restrict__ Wh1,
                 const float* __restrict__ bh1, const float* __restrict__ Wh2,
                 const float* __restrict__ bh2, float* __restrict__ scores, int N) {
    int n = blockIdx.x;
    int j = threadIdx.x;
    __shared__ float er[128];
    __shared__ float zs[64];
    er[j]      = emb[(size_t)n * 128 + j];
    er[j + 64] = emb[(size_t)n * 128 + 64 + j];
    __syncthreads();
    const float* w = Wh1 + j * 128;
    float s = 0.f;
    #pragma unroll 8
    for (int k = 0; k < 128; k++) s += er[k] * w[k];
    s += bh1[j];
    s = fmaxf(s, 0.f);
    zs[j] = s * Wh2[j];
    __syncthreads();
    if (j < 32) {
        float v = zs[j] + zs[j + 32];
        #pragma unroll
        for (int o = 16; o; o >>= 1) v += __shfl_down_sync(0xffffffffu, v, o);
        if (j == 0) scores[n] = 1.f / (1.f + __expf(-(v + bh2[0])));
    }
}

// ---------------------------------------------------------------------------

extern "C" void kernel_launch(void* const* d_in, const int* in_sizes, int n_in,
                              void* d_out, int out_size) {
    const float* x  = (const float*)d_in[0];
    const int*   ei = (const int*)d_in[1];
    const float *W1 = (const float*)d_in[2],  *as1 = (const float*)d_in[3],
                *ad1 = (const float*)d_in[4], *b1 = (const float*)d_in[5];
    const float *W2 = (const float*)d_in[6],  *as2 = (const float*)d_in[7],
                *ad2 = (const float*)d_in[8], *b2 = (const float*)d_in[9];
    const float *W3 = (const float*)d_in[10], *as3 = (const float*)d_in[11],
                *ad3 = (const float*)d_in[12], *b3 = (const float*)d_in[13];
    const float *Wh1 = (const float*)d_in[14], *bh1 = (const float*)d_in[15],
                *Wh2 = (const float*)d_in[16], *bh2 = (const float*)d_in[17];
    float* out = (float*)d_out;

    const int N = in_sizes[0] / 256;
    const int E = in_sizes[1] / 2;
    const int ET = E + N;

    float4 *gh4, *gout4, *wc4;
    float *snp, *dnp;
    int *cnt, *rp, *cursor, *ssrc, *bsum;
    cudaGetSymbolAddress((void**)&gh4,    g_h_buf4);
    cudaGetSymbolAddress((void**)&gout4,  g_out_buf4);
    cudaGetSymbolAddress((void**)&wc4,    g_wc4);
    cudaGetSymbolAddress((void**)&snp,    g_sn_buf);
    cudaGetSymbolAddress((void**)&dnp,    g_dn_buf);
    cudaGetSymbolAddress((void**)&cnt,    g_cnt);
    cudaGetSymbolAddress((void**)&rp,     g_rp);
    cudaGetSymbolAddress((void**)&cursor, g_cursor);
    cudaGetSymbolAddress((void**)&ssrc,   g_ssrc);
    cudaGetSymbolAddress((void**)&bsum,   g_bsum);
    float* gout = (float*)gout4;
    __half* gh_half = (__half*)gh4;

    auto cdiv = [](int a, int b) { return (a + b - 1) / b; };

    constexpr int SMEM_GEMM = 3 * 128 * 20 * 2 * 4;   // 61440 B
    cudaFuncSetAttribute(sgemm_tf32,
                         cudaFuncAttributeMaxDynamicSharedMemorySize, SMEM_GEMM);

    // ---- pre-round weights + x to tf32 bits ----
    float* wc1 = (float*)wc4;
    float* wc2 = wc1 + 131072;
    float* wc3 = wc2 + 262144;
    cvt4_k<<<cdiv(131072 / 4, 256), 256>>>((const float4*)W1, (float4*)wc1, 131072 / 4);
    cvt4_k<<<cdiv(262144 / 4, 256), 256>>>((const float4*)W2, (float4*)wc2, 262144 / 4);
    cvt4_k<<<cdiv(65536 / 4, 256), 256>>>((const float4*)W3, (float4*)wc3, 65536 / 4);
    float* xc = gout;
    cvt4_k<<<cdiv(N * 64, 256), 256>>>((const float4*)x, (float4*)xc, N * 64);

    // ---- CSR build (once; reused by all 3 layers) ----
    const int nb = cdiv(N, 1024);
    cudaMemsetAsync(cnt, 0, (size_t)N * 4);
    hist_k<<<cdiv(ET, 256), 256>>>(ei, cnt, E, N);
    scan1<<<nb, 1024>>>(cnt, rp, bsum, N);
    scan2<<<1, 1024>>>(bsum, nb);
    scan3<<<cdiv(N + 1, 256), 256>>>(rp, bsum, cursor, N, ET);
    scatter_k<<<cdiv(ET, 256), 256>>>(ei, cursor, ssrc, E, N);

    // ---- generic GAT layer ----
    auto run_layer = [&](const float* fin, int Fin, const float* W,
                         const float* as, const float* ad, const float* bb,
                         int H, int act, float* finalout) {
        const int HC = H * 128;
        dim3 gg(cdiv(HC, 128), cdiv(N, 128));
        sgemm_tf32<<<gg, 256, SMEM_GEMM>>>(fin, W, gh_half, N, HC, Fin);
        compute_sd<<<cdiv(N * H * 32, 256), 256>>>(
            (const uint2*)gh_half, (const float4*)as, (const float4*)ad,
            snp, dnp, N, H);
        int agg_grid = cdiv(N * 32, 256);
        if (H == 4)
            aggregate_h<4><<<agg_grid, 256>>>(
                rp, ssrc, (const uint2*)gh_half, snp, dnp,
                (const float4*)bb, act, (float4*)finalout, N);
        else
            aggregate_h<1><<<agg_grid, 256>>>(
                rp, ssrc, (const uint2*)gh_half, snp, dnp,
                (const float4*)bb, act, (float4*)finalout, N);
    };

    run_layer(xc,   256, wc1, as1, ad1, b1, 4, 1, gout);
    run_layer(gout, 512, wc2, as2, ad2, b2, 4, 1, gout);
    run_layer(gout, 512, wc3, as3, ad3, b3, 1, 0, out);

    head_kernel<<<N, 64>>>(out, Wh1, bh1, Wh2, bh2, out + (size_t)N * 128, N);
}